// round 6
// baseline (speedup 1.0000x reference)
#include <cuda_runtime.h>
#include <cstdint>

// Problem constants
static constexpr int Bn   = 2;
static constexpr int Din  = 18;
static constexpr int Dout = 16;
static constexpr int Hn   = 128;
static constexpr int Wn   = 128;
static constexpr int VOX  = 128;                 // voxels per CTA = one W row
static constexpr int ROWF = 125;                 // floats per voxel row (5^3)
static constexpr int BUF_WORDS = VOX * ROWF;     // 16000 floats = 64000 B
static constexpr int WARP_BYTES = 32 * ROWF * 4; // 16000 B per warp slice
static constexpr int SMEM_BYTES = BUF_WORDS * 4 + 4 * 8;  // buf + 4 mbarriers

// ---------------- TMA bulk + mbarrier helpers ----------------
__device__ __forceinline__ void mbar_init1(uint32_t mbar) {
    asm volatile("mbarrier.init.shared.b64 [%0], 1;" :: "r"(mbar) : "memory");
}
__device__ __forceinline__ void fence_proxy_async_cta() {
    asm volatile("fence.proxy.async.shared::cta;" ::: "memory");
}
__device__ __forceinline__ void bulk_copy(uint32_t sdst, const void* gsrc,
                                          uint32_t bytes, uint32_t mbar) {
    asm volatile("mbarrier.arrive.expect_tx.shared.b64 _, [%0], %1;"
                 :: "r"(mbar), "r"(bytes) : "memory");
    asm volatile("cp.async.bulk.shared::cta.global.mbarrier::complete_tx::bytes "
                 "[%0], [%1], %2, [%3];"
                 :: "r"(sdst), "l"(gsrc), "r"(bytes), "r"(mbar) : "memory");
}
__device__ __forceinline__ void mbar_wait(uint32_t mbar, uint32_t parity) {
    asm volatile(
        "{\n\t"
        ".reg .pred P;\n\t"
        "WAIT_%=:\n\t"
        "mbarrier.try_wait.parity.acquire.cta.shared::cta.b64 P, [%0], %1, 0x989680;\n\t"
        "@P bra WAIT_DONE_%=;\n\t"
        "bra WAIT_%=;\n\t"
        "WAIT_DONE_%=:\n\t"
        "}"
        :: "r"(mbar), "r"(parity) : "memory");
}

// Full 5^3 -> 3^3 valid cross-correlation, input-stationary.
// 125 LDS.32 (conflict-free: lane word-stride 125 is odd) + 729 FMA.
__device__ __forceinline__ void conv_acc(const float* __restrict__ s,
                                         const float (&wk)[27], float (&acc)[27]) {
#pragma unroll
    for (int p = 0; p < 5; p++)
#pragma unroll
    for (int q = 0; q < 5; q++)
#pragma unroll
    for (int r = 0; r < 5; r++) {
        float v = s[p * 25 + q * 5 + r];
#pragma unroll
        for (int a = 0; a < 3; a++) {
            if (p - a < 0 || p - a > 2) continue;
#pragma unroll
            for (int bq = 0; bq < 3; bq++) {
                if (q - bq < 0 || q - bq > 2) continue;
#pragma unroll
                for (int cr = 0; cr < 3; cr++) {
                    if (r - cr < 0 || r - cr > 2) continue;
                    acc[(a * 3 + bq) * 3 + cr] =
                        fmaf(v, wk[((p - a) * 3 + (q - bq)) * 3 + (r - cr)],
                             acc[(a * 3 + bq) * 3 + cr]);
                }
            }
        }
    }
}

__global__ void __launch_bounds__(VOX, 3)
jbf_kernel(const float* __restrict__ x,
           const float* __restrict__ dom,
           const float* __restrict__ gui,
           const float* __restrict__ dom_w,
           const float* __restrict__ dom_b,
           const float* __restrict__ rng_w,
           const float* __restrict__ rng_b,
           float* __restrict__ out)
{
    extern __shared__ float sbuf[];     // [VOX][125] + 4 mbarriers at the end

    const int tid  = threadIdx.x;
    const int lane = tid & 31;
    const int wid  = tid >> 5;
    const int v0   = wid << 5;          // first voxel of this warp (CTA-local)
    const int cta  = blockIdx.x;
    const int h = cta & (Hn - 1);
    const int d = (cta >> 7) & (Dout - 1);
    const int b = cta >> 11;
    const long long m0 = (long long)cta * VOX;

    const uint32_t sm32  = (uint32_t)__cvta_generic_to_shared(sbuf);
    const uint32_t swarp = sm32 + (uint32_t)v0 * ROWF * 4u;          // 16000B slice
    const uint32_t mbar  = sm32 + (uint32_t)BUF_WORDS * 4u + wid * 8u;
    const float* srow = sbuf + tid * ROWF;
    const float* gwarp_dom = dom + (m0 + v0) * ROWF;
    const float* gwarp_gui = gui + (m0 + v0) * ROWF;

    // ---- Per-warp mbarrier init + phase-1 bulk copy (no cross-warp sync) ----
    if (lane == 0) mbar_init1(mbar);
    fence_proxy_async_cta();
    __syncwarp();
    if (lane == 0) bulk_copy(swarp, gwarp_dom, WARP_BYTES, mbar);

    float wk[27];
#pragma unroll
    for (int t = 0; t < 27; t++) wk[t] = dom_w[t];

    // ---- Phase 1: domain conv ----
    mbar_wait(mbar, 0);

    float dk[27];
#pragma unroll
    for (int o = 0; o < 27; o++) dk[o] = 0.0f;
    conv_acc(srow, wk, dk);

    // ---- Phase 2: restage with guide (same slice), range conv ----
    __syncwarp();                 // all conv-1 LDS of this warp retired
    fence_proxy_async_cta();      // order generic reads before async-proxy write
    if (lane == 0) bulk_copy(swarp, gwarp_gui, WARP_BYTES, mbar);

#pragma unroll
    for (int t = 0; t < 27; t++) wk[t] = rng_w[t];

    mbar_wait(mbar, 1);

    float rk[27];
#pragma unroll
    for (int o = 0; o < 27; o++) rk[o] = 0.0f;
    conv_acc(srow, wk, rk);

    // ---- Fused epilogue: ReLU, bilateral weight, weighted x-sum, normalize.
    //      x read directly (coalesced, L2-resident). ----
    const float db = dom_b[0];
    const float rb = rng_b[0];
    const int w = tid;                  // W == VOX: thread == column
    float num = 0.0f, den = 0.0f;
#pragma unroll
    for (int i = 0; i < 3; i++)
#pragma unroll
    for (int j = 0; j < 3; j++) {
        const int hh = h + j - 1;
        const bool hok = (hh >= 0) && (hh < Hn);
        const long long base = (((long long)b * Din + (d + i)) << 14) + (hh << 7);
#pragma unroll
        for (int l = 0; l < 3; l++) {
            const int o = (i * 3 + j) * 3 + l;
            float dko = fmaxf(dk[o] + db, 0.0f);
            float rko = fmaxf(rk[o] + rb, 0.0f);
            float wt  = fmaf(dko, rko, 1e-10f);
            const int ww = w + l - 1;
            float xv = (hok && ww >= 0 && ww < Wn) ? x[base + ww] : 0.0f;
            num = fmaf(wt, xv, num);
            den += wt;
        }
    }

    out[m0 + tid] = num / den;
}

extern "C" void kernel_launch(void* const* d_in, const int* in_sizes, int n_in,
                              void* d_out, int out_size) {
    const float* x     = (const float*)d_in[0];
    const float* dom   = (const float*)d_in[1];
    const float* gui   = (const float*)d_in[2];
    const float* dom_w = (const float*)d_in[3];
    const float* dom_b = (const float*)d_in[4];
    const float* rng_w = (const float*)d_in[5];
    const float* rng_b = (const float*)d_in[6];
    float* out = (float*)d_out;

    cudaFuncSetAttribute(jbf_kernel, cudaFuncAttributeMaxDynamicSharedMemorySize,
                         SMEM_BYTES);

    const int grid = (Bn * Dout * Hn * Wn) / VOX;   // 4096 CTAs
    jbf_kernel<<<grid, VOX, SMEM_BYTES>>>(x, dom, gui, dom_w, dom_b, rng_w, rng_b, out);
}

// round 7
// speedup vs baseline: 1.0228x; 1.0228x over previous
#include <cuda_runtime.h>
#include <cstdint>

// Problem constants
static constexpr int Bn   = 2;
static constexpr int Din  = 18;
static constexpr int Dout = 16;
static constexpr int Hn   = 128;
static constexpr int Wn   = 128;
static constexpr int TPB  = 64;                   // 2 warps per CTA
static constexpr int ROWF = 125;                  // floats per voxel row (5^3)
static constexpr int WARP_WORDS = 32 * ROWF;      // 4000 floats = 16000 B
static constexpr int WARP_BYTES = WARP_WORDS * 4;
static constexpr int BUF_WORDS  = 2 * TPB * ROWF; // dom+gui for 64 voxels = 64000 B
static constexpr int SMEM_BYTES = BUF_WORDS * 4 + 4 * 8;   // + 4 mbarriers

// ---------------- TMA bulk + mbarrier helpers ----------------
__device__ __forceinline__ void mbar_init1(uint32_t mbar) {
    asm volatile("mbarrier.init.shared.b64 [%0], 1;" :: "r"(mbar) : "memory");
}
__device__ __forceinline__ void fence_proxy_async_cta() {
    asm volatile("fence.proxy.async.shared::cta;" ::: "memory");
}
__device__ __forceinline__ void bulk_copy(uint32_t sdst, const void* gsrc,
                                          uint32_t bytes, uint32_t mbar) {
    asm volatile("mbarrier.arrive.expect_tx.shared.b64 _, [%0], %1;"
                 :: "r"(mbar), "r"(bytes) : "memory");
    asm volatile("cp.async.bulk.shared::cta.global.mbarrier::complete_tx::bytes "
                 "[%0], [%1], %2, [%3];"
                 :: "r"(sdst), "l"(gsrc), "r"(bytes), "r"(mbar) : "memory");
}
__device__ __forceinline__ void mbar_wait(uint32_t mbar, uint32_t parity) {
    asm volatile(
        "{\n\t"
        ".reg .pred P;\n\t"
        "WAIT_%=:\n\t"
        "mbarrier.try_wait.parity.acquire.cta.shared::cta.b64 P, [%0], %1, 0x989680;\n\t"
        "@P bra WAIT_DONE_%=;\n\t"
        "bra WAIT_%=;\n\t"
        "WAIT_DONE_%=:\n\t"
        "}"
        :: "r"(mbar), "r"(parity) : "memory");
}

// Full 5^3 -> 3^3 valid cross-correlation, input-stationary.
// 125 LDS.32 (conflict-free: lane word-stride 125 is odd) + 729 FMA.
__device__ __forceinline__ void conv_acc(const float* __restrict__ s,
                                         const float (&wk)[27], float (&acc)[27]) {
#pragma unroll
    for (int p = 0; p < 5; p++)
#pragma unroll
    for (int q = 0; q < 5; q++)
#pragma unroll
    for (int r = 0; r < 5; r++) {
        float v = s[p * 25 + q * 5 + r];
#pragma unroll
        for (int a = 0; a < 3; a++) {
            if (p - a < 0 || p - a > 2) continue;
#pragma unroll
            for (int bq = 0; bq < 3; bq++) {
                if (q - bq < 0 || q - bq > 2) continue;
#pragma unroll
                for (int cr = 0; cr < 3; cr++) {
                    if (r - cr < 0 || r - cr > 2) continue;
                    acc[(a * 3 + bq) * 3 + cr] =
                        fmaf(v, wk[((p - a) * 3 + (q - bq)) * 3 + (r - cr)],
                             acc[(a * 3 + bq) * 3 + cr]);
                }
            }
        }
    }
}

__global__ void __launch_bounds__(TPB, 3)
jbf_kernel(const float* __restrict__ x,
           const float* __restrict__ dom,
           const float* __restrict__ gui,
           const float* __restrict__ dom_w,
           const float* __restrict__ dom_b,
           const float* __restrict__ rng_w,
           const float* __restrict__ rng_b,
           float* __restrict__ out)
{
    extern __shared__ float sbuf[];
    // layout (words): [0, 8000)  dom rows for 64 voxels (warp slices 0,1)
    //                 [8000,16000) gui rows              (warp slices 0,1)
    //                 then 4 mbarriers (8B each)

    const int tid  = threadIdx.x;
    const int lane = tid & 31;
    const int wid  = tid >> 5;               // 0 or 1
    const long long m0 = (long long)blockIdx.x * TPB;
    const long long m  = m0 + tid;           // global voxel id
    const int w = (int)(m & (Wn - 1));
    const int h = (int)((m >> 7) & (Hn - 1));
    const int d = (int)((m >> 14) & (Dout - 1));
    const int b = (int)(m >> 18);

    const uint32_t sm32 = (uint32_t)__cvta_generic_to_shared(sbuf);
    const uint32_t s_dom = sm32 + (uint32_t)(wid * WARP_BYTES);
    const uint32_t s_gui = sm32 + (uint32_t)(TPB * ROWF * 4 + wid * WARP_BYTES);
    const uint32_t mb_dom = sm32 + (uint32_t)BUF_WORDS * 4u + (wid * 2 + 0) * 8u;
    const uint32_t mb_gui = sm32 + (uint32_t)BUF_WORDS * 4u + (wid * 2 + 1) * 8u;

    const long long v0 = m0 + (wid << 5);    // first voxel of this warp

    // ---- Prologue: init per-warp mbarriers, launch BOTH bulk copies ----
    if (lane == 0) {
        mbar_init1(mb_dom);
        mbar_init1(mb_gui);
        fence_proxy_async_cta();
        bulk_copy(s_dom, dom + v0 * ROWF, WARP_BYTES, mb_dom);
        bulk_copy(s_gui, gui + v0 * ROWF, WARP_BYTES, mb_gui);
    }
    __syncwarp();

    float wk[27];
#pragma unroll
    for (int t = 0; t < 27; t++) wk[t] = dom_w[t];

    // ---- Phase 1: domain conv ----
    mbar_wait(mb_dom, 0);

    float dk[27];
#pragma unroll
    for (int o = 0; o < 27; o++) dk[o] = 0.0f;
    conv_acc(sbuf + tid * ROWF, wk, dk);

    // ---- Phase 2: range conv (separate buffer -> no WAR, likely already here) ----
#pragma unroll
    for (int t = 0; t < 27; t++) wk[t] = rng_w[t];

    mbar_wait(mb_gui, 0);

    float rk[27];
#pragma unroll
    for (int o = 0; o < 27; o++) rk[o] = 0.0f;
    conv_acc(sbuf + TPB * ROWF + tid * ROWF, wk, rk);

    // ---- Fused epilogue: ReLU, bilateral weight, weighted x-sum, normalize.
    //      x read directly (coalesced, L2-resident). ----
    const float db = dom_b[0];
    const float rb = rng_b[0];
    float num = 0.0f, den = 0.0f;
#pragma unroll
    for (int i = 0; i < 3; i++)
#pragma unroll
    for (int j = 0; j < 3; j++) {
        const int hh = h + j - 1;
        const bool hok = (hh >= 0) && (hh < Hn);
        const long long base = (((long long)b * Din + (d + i)) << 14) + (hh << 7);
#pragma unroll
        for (int l = 0; l < 3; l++) {
            const int o = (i * 3 + j) * 3 + l;
            float dko = fmaxf(dk[o] + db, 0.0f);
            float rko = fmaxf(rk[o] + rb, 0.0f);
            float wt  = fmaf(dko, rko, 1e-10f);
            const int ww = w + l - 1;
            float xv = (hok && ww >= 0 && ww < Wn) ? x[base + ww] : 0.0f;
            num = fmaf(wt, xv, num);
            den += wt;
        }
    }

    out[m] = num / den;
}

extern "C" void kernel_launch(void* const* d_in, const int* in_sizes, int n_in,
                              void* d_out, int out_size) {
    const float* x     = (const float*)d_in[0];
    const float* dom   = (const float*)d_in[1];
    const float* gui   = (const float*)d_in[2];
    const float* dom_w = (const float*)d_in[3];
    const float* dom_b = (const float*)d_in[4];
    const float* rng_w = (const float*)d_in[5];
    const float* rng_b = (const float*)d_in[6];
    float* out = (float*)d_out;

    cudaFuncSetAttribute(jbf_kernel, cudaFuncAttributeMaxDynamicSharedMemorySize,
                         SMEM_BYTES);

    const int grid = (Bn * Dout * Hn * Wn) / TPB;   // 8192 CTAs of 64 threads
    jbf_kernel<<<grid, TPB, SMEM_BYTES>>>(x, dom, gui, dom_w, dom_b, rng_w, rng_b, out);
}

// round 8
// speedup vs baseline: 1.0459x; 1.0226x over previous
#include <cuda_runtime.h>
#include <cstdint>

// Problem constants
static constexpr int Bn   = 2;
static constexpr int Din  = 18;
static constexpr int Dout = 16;
static constexpr int Hn   = 128;
static constexpr int Wn   = 128;
static constexpr int TPB  = 32;                   // ONE warp per CTA
static constexpr int ROWF = 125;                  // floats per voxel row (5^3)
static constexpr int WARP_WORDS = 32 * ROWF;      // 4000 floats = 16000 B
static constexpr int WARP_BYTES = WARP_WORDS * 4;
static constexpr int SMEM_BYTES = 2 * WARP_BYTES + 16;   // dom + gui + 2 mbarriers

// ---------------- TMA bulk + mbarrier helpers ----------------
__device__ __forceinline__ void mbar_init1(uint32_t mbar) {
    asm volatile("mbarrier.init.shared.b64 [%0], 1;" :: "r"(mbar) : "memory");
}
__device__ __forceinline__ void fence_proxy_async_cta() {
    asm volatile("fence.proxy.async.shared::cta;" ::: "memory");
}
__device__ __forceinline__ void bulk_copy(uint32_t sdst, const void* gsrc,
                                          uint32_t bytes, uint32_t mbar) {
    asm volatile("mbarrier.arrive.expect_tx.shared.b64 _, [%0], %1;"
                 :: "r"(mbar), "r"(bytes) : "memory");
    asm volatile("cp.async.bulk.shared::cta.global.mbarrier::complete_tx::bytes "
                 "[%0], [%1], %2, [%3];"
                 :: "r"(sdst), "l"(gsrc), "r"(bytes), "r"(mbar) : "memory");
}
__device__ __forceinline__ void mbar_wait(uint32_t mbar, uint32_t parity) {
    asm volatile(
        "{\n\t"
        ".reg .pred P;\n\t"
        "WAIT_%=:\n\t"
        "mbarrier.try_wait.parity.acquire.cta.shared::cta.b64 P, [%0], %1, 0x989680;\n\t"
        "@P bra WAIT_DONE_%=;\n\t"
        "bra WAIT_%=;\n\t"
        "WAIT_DONE_%=:\n\t"
        "}"
        :: "r"(mbar), "r"(parity) : "memory");
}

// Full 5^3 -> 3^3 valid cross-correlation, input-stationary.
// 125 LDS.32 (conflict-free: lane word-stride 125 is odd) + 729 FMA.
__device__ __forceinline__ void conv_acc(const float* __restrict__ s,
                                         const float (&wk)[27], float (&acc)[27]) {
#pragma unroll
    for (int p = 0; p < 5; p++)
#pragma unroll
    for (int q = 0; q < 5; q++)
#pragma unroll
    for (int r = 0; r < 5; r++) {
        float v = s[p * 25 + q * 5 + r];
#pragma unroll
        for (int a = 0; a < 3; a++) {
            if (p - a < 0 || p - a > 2) continue;
#pragma unroll
            for (int bq = 0; bq < 3; bq++) {
                if (q - bq < 0 || q - bq > 2) continue;
#pragma unroll
                for (int cr = 0; cr < 3; cr++) {
                    if (r - cr < 0 || r - cr > 2) continue;
                    acc[(a * 3 + bq) * 3 + cr] =
                        fmaf(v, wk[((p - a) * 3 + (q - bq)) * 3 + (r - cr)],
                             acc[(a * 3 + bq) * 3 + cr]);
                }
            }
        }
    }
}

__global__ void __launch_bounds__(TPB, 7)
jbf_kernel(const float* __restrict__ x,
           const float* __restrict__ dom,
           const float* __restrict__ gui,
           const float* __restrict__ dom_w,
           const float* __restrict__ dom_b,
           const float* __restrict__ rng_w,
           const float* __restrict__ rng_b,
           float* __restrict__ out)
{
    extern __shared__ float sbuf[];
    // words: [0,4000) dom rows (32 voxels), [4000,8000) gui rows, then 2 mbarriers

    const int lane = threadIdx.x;
    const long long m0 = (long long)blockIdx.x * TPB;   // first voxel of this CTA
    const long long m  = m0 + lane;                     // this thread's voxel
    const int w = (int)(m & (Wn - 1));
    const int h = (int)((m >> 7) & (Hn - 1));
    const int d = (int)((m >> 14) & (Dout - 1));
    const int b = (int)(m >> 18);

    const uint32_t sm32   = (uint32_t)__cvta_generic_to_shared(sbuf);
    const uint32_t s_dom  = sm32;
    const uint32_t s_gui  = sm32 + (uint32_t)WARP_BYTES;
    const uint32_t mb_dom = sm32 + 2u * WARP_BYTES;
    const uint32_t mb_gui = mb_dom + 8u;

    // ---- Prologue: init mbarriers, launch BOTH bulk copies immediately ----
    if (lane == 0) {
        mbar_init1(mb_dom);
        mbar_init1(mb_gui);
        fence_proxy_async_cta();
        bulk_copy(s_dom, dom + m0 * ROWF, WARP_BYTES, mb_dom);
        bulk_copy(s_gui, gui + m0 * ROWF, WARP_BYTES, mb_gui);
    }
    __syncwarp();

    float wk[27];
#pragma unroll
    for (int t = 0; t < 27; t++) wk[t] = dom_w[t];

    // ---- Phase 1: domain conv ----
    mbar_wait(mb_dom, 0);

    float dk[27];
#pragma unroll
    for (int o = 0; o < 27; o++) dk[o] = 0.0f;
    conv_acc(sbuf + lane * ROWF, wk, dk);

    // ---- Phase 2: range conv (separate buffer, copy long since issued) ----
#pragma unroll
    for (int t = 0; t < 27; t++) wk[t] = rng_w[t];

    mbar_wait(mb_gui, 0);

    float rk[27];
#pragma unroll
    for (int o = 0; o < 27; o++) rk[o] = 0.0f;
    conv_acc(sbuf + WARP_WORDS + lane * ROWF, wk, rk);

    // ---- Fused epilogue: ReLU, bilateral weight, weighted x-sum, normalize.
    //      x read directly (coalesced, L2-resident). ----
    const float db = dom_b[0];
    const float rb = rng_b[0];
    float num = 0.0f, den = 0.0f;
#pragma unroll
    for (int i = 0; i < 3; i++)
#pragma unroll
    for (int j = 0; j < 3; j++) {
        const int hh = h + j - 1;
        const bool hok = (hh >= 0) && (hh < Hn);
        const long long base = (((long long)b * Din + (d + i)) << 14) + (hh << 7);
#pragma unroll
        for (int l = 0; l < 3; l++) {
            const int o = (i * 3 + j) * 3 + l;
            float dko = fmaxf(dk[o] + db, 0.0f);
            float rko = fmaxf(rk[o] + rb, 0.0f);
            float wt  = fmaf(dko, rko, 1e-10f);
            const int ww = w + l - 1;
            float xv = (hok && ww >= 0 && ww < Wn) ? x[base + ww] : 0.0f;
            num = fmaf(wt, xv, num);
            den += wt;
        }
    }

    out[m] = num / den;
}

extern "C" void kernel_launch(void* const* d_in, const int* in_sizes, int n_in,
                              void* d_out, int out_size) {
    const float* x     = (const float*)d_in[0];
    const float* dom   = (const float*)d_in[1];
    const float* gui   = (const float*)d_in[2];
    const float* dom_w = (const float*)d_in[3];
    const float* dom_b = (const float*)d_in[4];
    const float* rng_w = (const float*)d_in[5];
    const float* rng_b = (const float*)d_in[6];
    float* out = (float*)d_out;

    cudaFuncSetAttribute(jbf_kernel, cudaFuncAttributeMaxDynamicSharedMemorySize,
                         SMEM_BYTES);

    const int grid = (Bn * Dout * Hn * Wn) / TPB;   // 16384 CTAs of 32 threads
    jbf_kernel<<<grid, TPB, SMEM_BYTES>>>(x, dom, gui, dom_w, dom_b, rng_w, rng_b, out);
}